// round 1
// baseline (speedup 1.0000x reference)
#include <cuda_runtime.h>
#include <cuda_bf16.h>
#include <cstdint>

// Problem constants
#define B_   1024
#define P_   24
#define H_   2048
#define K1_  4096   // H*R
#define N1_  2048   // H
#define K2_  2048
#define N2_  1024   // H/2
#define OUTP 4

// Scratch (allocation-free rule: __device__ globals)
__device__ float g_h1[(size_t)P_ * B_ * N1_];   // [p][b][n] fp32, 201 MB
__device__ float g_h2[(size_t)P_ * B_ * N2_];   // [p][b][n] fp32, 100 MB

// ---------------------------------------------------------------------------
// helpers
// ---------------------------------------------------------------------------
__device__ __forceinline__ uint32_t f2tf(float x) {
    uint32_t r;
    asm("cvt.rna.tf32.f32 %0, %1;" : "=r"(r) : "f"(x));
    return r;
}

__device__ __forceinline__ void mma_tf32(float* c, const uint32_t* a, const uint32_t* b) {
    asm volatile(
        "mma.sync.aligned.m16n8k8.row.col.f32.tf32.tf32.f32 "
        "{%0,%1,%2,%3}, {%4,%5,%6,%7}, {%8,%9}, {%0,%1,%2,%3};"
        : "+f"(c[0]), "+f"(c[1]), "+f"(c[2]), "+f"(c[3])
        : "r"(a[0]), "r"(a[1]), "r"(a[2]), "r"(a[3]), "r"(b[0]), "r"(b[1]));
}

__device__ __forceinline__ void cp_async16(uint32_t smem_addr, const void* gptr, int src_size) {
    asm volatile("cp.async.cg.shared.global [%0], [%1], 16, %2;"
                 :: "r"(smem_addr), "l"(gptr), "r"(src_size));
}
__device__ __forceinline__ void cp_commit() {
    asm volatile("cp.async.commit_group;" ::: "memory");
}
template <int N>
__device__ __forceinline__ void cp_wait() {
    asm volatile("cp.async.wait_group %0;" :: "n"(N) : "memory");
}

__device__ __forceinline__ float gelu_exact(float v) {
    return 0.5f * v * (1.0f + erff(v * 0.7071067811865476f));
}

// ---------------------------------------------------------------------------
// Grouped GEMM + GELU.
// MODE 0: A is the windowed input x[B,P,H]:  Xw[p](b, k) = k<H ? x[b,p,k]
//         : (p+1<P ? x[b,p+1,k-H] : 0).   K=4096, N=2048, C = g_h1.
// MODE 1: A = g_h1 [p][b][k] contiguous.    K=2048, N=1024, C = g_h2.
// W is [P][K][N] row-major (N contiguous). C[p][b][n] = gelu(A@W + bias).
// CTA tile 128x128, K-tile 32, 256 threads (8 warps, 4x2, each 32x64).
// ---------------------------------------------------------------------------
#define BM 128
#define BN 128
#define BK 32
#define ASTR 36            // A smem row stride (floats): 16B-aligned, conflict-free
#define BSTR 136           // B smem row stride (floats): 16B-aligned, banks k*8+n
#define ASZ (BM * ASTR)    // per-buffer
#define BSZ (BK * BSTR)
#define SMEM_BYTES ((2 * ASZ + 2 * BSZ) * 4)   // 71680

template <int MODE>
__global__ void __launch_bounds__(256)
gemm_act_kernel(const float* __restrict__ A, const float* __restrict__ W,
                const float* __restrict__ bias, float* __restrict__ C,
                int K, int N) {
    extern __shared__ float smem[];
    float* Abuf = smem;                 // [2][BM][ASTR]
    float* Bbuf = smem + 2 * ASZ;       // [2][BK][BSTR]

    const int p    = blockIdx.z;
    const int bm   = blockIdx.y;
    const int bn   = blockIdx.x;
    const int tid  = threadIdx.x;
    const int warp = tid >> 5;
    const int lane = tid & 31;
    const int warpM = warp >> 1;   // 0..3
    const int warpN = warp & 1;    // 0..1

    float acc[2][8][4];
#pragma unroll
    for (int mf = 0; mf < 2; mf++)
#pragma unroll
        for (int nf = 0; nf < 8; nf++)
#pragma unroll
            for (int i = 0; i < 4; i++) acc[mf][nf][i] = 0.f;

    const float* Wp = W + (size_t)p * K * N + (size_t)bn * BN;

    auto load_tiles = [&](int buf, int kt) {
#pragma unroll
        for (int i = 0; i < 4; i++) {
            int c = tid + i * 256;          // 0..1023
            // ---- A chunk: m = c/8, k = (c%8)*4
            int m  = c >> 3;
            int kl = (c & 7) * 4;
            int kg = kt * BK + kl;
            const float* ga;
            int sz = 16;
            if (MODE == 0) {
                int half = (kg >= H_) ? 1 : 0;
                int pp   = p + half;
                int kk   = kg - half * H_;
                if (pp >= P_) { pp = P_ - 1; sz = 0; }
                ga = A + ((size_t)(bm * BM + m) * P_ + pp) * H_ + kk;
            } else {
                ga = A + ((size_t)p * B_ + bm * BM + m) * (size_t)K + kg;
            }
            uint32_t sa = (uint32_t)__cvta_generic_to_shared(
                &Abuf[buf * ASZ + m * ASTR + kl]);
            cp_async16(sa, ga, sz);

            // ---- B chunk: k = c/32, n = (c%32)*4
            int kb = c >> 5;
            int nb = (c & 31) * 4;
            const float* gb = Wp + (size_t)(kt * BK + kb) * N + nb;
            uint32_t sb = (uint32_t)__cvta_generic_to_shared(
                &Bbuf[buf * BSZ + kb * BSTR + nb]);
            cp_async16(sb, gb, 16);
        }
    };

    const int NKT = K / BK;
    load_tiles(0, 0);
    cp_commit();

    const int g  = lane >> 2;
    const int cc = lane & 3;

    for (int kt = 0; kt < NKT; ++kt) {
        int cur = kt & 1;
        if (kt + 1 < NKT) {
            load_tiles(cur ^ 1, kt + 1);
            cp_commit();
            cp_wait<1>();
        } else {
            cp_wait<0>();
        }
        __syncthreads();

        const float* As = Abuf + cur * ASZ;
        const float* Bs = Bbuf + cur * BSZ;
#pragma unroll
        for (int ks = 0; ks < 4; ks++) {
            int k0 = ks * 8;
            uint32_t a[2][4], b[8][2];
#pragma unroll
            for (int mf = 0; mf < 2; mf++) {
                int row = warpM * 32 + mf * 16 + g;
                a[mf][0] = f2tf(As[row * ASTR + k0 + cc]);
                a[mf][1] = f2tf(As[(row + 8) * ASTR + k0 + cc]);
                a[mf][2] = f2tf(As[row * ASTR + k0 + 4 + cc]);
                a[mf][3] = f2tf(As[(row + 8) * ASTR + k0 + 4 + cc]);
            }
#pragma unroll
            for (int nf = 0; nf < 8; nf++) {
                int col = warpN * 64 + nf * 8 + g;
                b[nf][0] = f2tf(Bs[(k0 + cc) * BSTR + col]);
                b[nf][1] = f2tf(Bs[(k0 + 4 + cc) * BSTR + col]);
            }
#pragma unroll
            for (int mf = 0; mf < 2; mf++)
#pragma unroll
                for (int nf = 0; nf < 8; nf++)
                    mma_tf32(acc[mf][nf], a[mf], b[nf]);
        }
        __syncthreads();
    }

    // Epilogue: bias + exact GELU, fp32 store.
    const int c2 = (lane & 3) * 2;
#pragma unroll
    for (int mf = 0; mf < 2; mf++) {
#pragma unroll
        for (int nf = 0; nf < 8; nf++) {
            int m = bm * BM + warpM * 32 + mf * 16 + g;
            int n = bn * BN + warpN * 64 + nf * 8 + c2;
            float bv0 = bias[p * N + n];
            float bv1 = bias[p * N + n + 1];
            size_t base  = ((size_t)p * B_ + m) * (size_t)N + n;
            size_t base8 = base + (size_t)8 * N;
            C[base]      = gelu_exact(acc[mf][nf][0] + bv0);
            C[base + 1]  = gelu_exact(acc[mf][nf][1] + bv1);
            C[base8]     = gelu_exact(acc[mf][nf][2] + bv0);
            C[base8 + 1] = gelu_exact(acc[mf][nf][3] + bv1);
        }
    }
}

// ---------------------------------------------------------------------------
// Layer 3: out[b, p*4+o] = relu(sum_k h2[p][b][k] * W3[p][k][o] + b3[p][o])
// One block (128 threads) per (p, b).
// ---------------------------------------------------------------------------
__global__ void l3_kernel(const float* __restrict__ h2, const float* __restrict__ W3,
                          const float* __restrict__ b3, float* __restrict__ out) {
    int p = blockIdx.x, b = blockIdx.y;
    int tid = threadIdx.x;
    const float* hrow = h2 + ((size_t)p * B_ + b) * N2_;
    const float* w    = W3 + (size_t)p * N2_ * OUTP;

    float a0 = 0.f, a1 = 0.f, a2 = 0.f, a3 = 0.f;
    for (int k = tid; k < N2_; k += 128) {
        float hv = hrow[k];
        const float* wr = w + k * OUTP;
        a0 += hv * wr[0]; a1 += hv * wr[1]; a2 += hv * wr[2]; a3 += hv * wr[3];
    }
#pragma unroll
    for (int off = 16; off; off >>= 1) {
        a0 += __shfl_down_sync(0xffffffffu, a0, off);
        a1 += __shfl_down_sync(0xffffffffu, a1, off);
        a2 += __shfl_down_sync(0xffffffffu, a2, off);
        a3 += __shfl_down_sync(0xffffffffu, a3, off);
    }
    __shared__ float sred[4][4];
    int warp = tid >> 5, lane = tid & 31;
    if (lane == 0) {
        sred[warp][0] = a0; sred[warp][1] = a1; sred[warp][2] = a2; sred[warp][3] = a3;
    }
    __syncthreads();
    if (tid < 4) {
        float s = sred[0][tid] + sred[1][tid] + sred[2][tid] + sred[3][tid]
                + b3[p * OUTP + tid];
        out[(size_t)b * (P_ * OUTP) + p * OUTP + tid] = fmaxf(s, 0.f);
    }
}

// ---------------------------------------------------------------------------
extern "C" void kernel_launch(void* const* d_in, const int* in_sizes, int n_in,
                              void* d_out, int out_size) {
    const float* x  = (const float*)d_in[0];
    const float* W1 = (const float*)d_in[1];
    const float* b1 = (const float*)d_in[2];
    const float* W2 = (const float*)d_in[3];
    const float* b2 = (const float*)d_in[4];
    const float* W3 = (const float*)d_in[5];
    const float* b3 = (const float*)d_in[6];
    float* out = (float*)d_out;

    float *h1, *h2;
    cudaGetSymbolAddress((void**)&h1, g_h1);
    cudaGetSymbolAddress((void**)&h2, g_h2);

    cudaFuncSetAttribute(gemm_act_kernel<0>,
                         cudaFuncAttributeMaxDynamicSharedMemorySize, SMEM_BYTES);
    cudaFuncSetAttribute(gemm_act_kernel<1>,
                         cudaFuncAttributeMaxDynamicSharedMemorySize, SMEM_BYTES);

    // Layer 1: [1024, 4096] @ [4096, 2048] per p, GELU
    gemm_act_kernel<0><<<dim3(N1_ / BN, B_ / BM, P_), 256, SMEM_BYTES>>>(
        x, W1, b1, h1, K1_, N1_);
    // Layer 2: [1024, 2048] @ [2048, 1024] per p, GELU
    gemm_act_kernel<1><<<dim3(N2_ / BN, B_ / BM, P_), 256, SMEM_BYTES>>>(
        h1, W2, b2, h2, K2_, N2_);
    // Layer 3: tiny N=4 + ReLU
    l3_kernel<<<dim3(P_, B_), 128>>>(h2, W3, b3, out);
}